// round 17
// baseline (speedup 1.0000x reference)
#include <cuda_runtime.h>
#include <cuda_bf16.h>
#include <cuda_fp16.h>
#include <math.h>

// Problem constants (fixed by dataset): N=100000, E=1600000, dims 128->64->32
#define IN_F  128
#define HID_F 64
#define OUT_F 32
#define N_MAX 100000
#define E_MAX 1600000
#define NB_MAX 512

typedef unsigned long long u64;
typedef unsigned int u32;

// ---- packed f32x2 helpers (sm_103a FFMA2/FADD2 via PTX) ----
__device__ __forceinline__ u64 pack2(float lo, float hi) {
    u64 r; asm("mov.b64 %0, {%1, %2};" : "=l"(r) : "f"(lo), "f"(hi)); return r;
}
__device__ __forceinline__ void fma2(u64& d, u64 a, u64 b) {
    asm("fma.rn.f32x2 %0, %1, %2, %0;" : "+l"(d) : "l"(a), "l"(b));
}
__device__ __forceinline__ void add2(u64& d, u64 a) {
    asm("add.rn.f32x2 %0, %0, %1;" : "+l"(d) : "l"(a));
}
__device__ __forceinline__ float2 unpack2(u64 v) {
    float2 f; asm("mov.b64 {%0, %1}, %2;" : "=f"(f.x), "=f"(f.y) : "l"(v)); return f;
}

// ---- device scratch (no cudaMalloc allowed) ----
// g_deg starts zero (static init) and is re-zeroed by gather2 (last reader).
__device__ int    g_deg    [N_MAX];                 // in-degree (self-loop excluded)
__device__ float  g_dinv   [N_MAX];
__device__ int    g_rowstart[N_MAX];
__device__ int    g_cursor [N_MAX];
__device__ int    g_bsum   [NB_MAX];
__device__ int    g_bofs   [NB_MAX];
__device__ int    g_csr    [E_MAX];                 // src index only (dinv folded into features)
__device__ __half g_H1h [(size_t)N_MAX * HID_F];    // dinv[n] * (x @ W1)[n]  (fp16)
__device__ float  g_agg1[(size_t)N_MAX * HID_F];    // relu(agg), fp32
__device__ __half g_H2h [(size_t)N_MAX * OUT_F];    // dinv[n] * (agg1 @ W2)[n] (fp16)

// ---------------------------------------------------------------------------
__global__ void k_edge_prep(const int* __restrict__ ei, int E) {
    int e = blockIdx.x * blockDim.x + threadIdx.x;
    if (e < E) atomicAdd(&g_deg[ei[E + e]], 1);
}

// SA: per-block indegree sums + dinv (deg = indeg + 1 self-loop)
__global__ __launch_bounds__(256) void k_scan_a(int N) {
    __shared__ int sh[256];
    int t = threadIdx.x;
    int n = blockIdx.x * 256 + t;
    int cnt = (n < N) ? g_deg[n] : 0;
    if (n < N) g_dinv[n] = rsqrtf((float)(cnt + 1));
    sh[t] = cnt;
    __syncthreads();
    for (int off = 128; off > 0; off >>= 1) {
        if (t < off) sh[t] += sh[t + off];
        __syncthreads();
    }
    if (t == 0) g_bsum[blockIdx.x] = sh[0];
}

__global__ __launch_bounds__(512) void k_scan_b(int NB) {
    __shared__ int sh[512];
    int t = threadIdx.x;
    int v = (t < NB) ? g_bsum[t] : 0;
    sh[t] = v;
    __syncthreads();
    for (int off = 1; off < 512; off <<= 1) {
        int add = (t >= off) ? sh[t - off] : 0;
        __syncthreads();
        sh[t] += add;
        __syncthreads();
    }
    if (t < NB) g_bofs[t] = sh[t] - v;
}

__global__ __launch_bounds__(256) void k_scan_c(int N) {
    __shared__ int sh[256];
    int t = threadIdx.x;
    int n = blockIdx.x * 256 + t;
    int v = (n < N) ? g_deg[n] : 0;
    sh[t] = v;
    __syncthreads();
    for (int off = 1; off < 256; off <<= 1) {
        int add = (t >= off) ? sh[t - off] : 0;
        __syncthreads();
        sh[t] += add;
        __syncthreads();
    }
    if (n < N) {
        int excl = sh[t] - v + g_bofs[blockIdx.x];
        g_rowstart[n] = excl;
        g_cursor[n]   = excl;
    }
}

// Fill CSR: src index only
__global__ void k_fill(const int* __restrict__ ei, int E) {
    int e = blockIdx.x * blockDim.x + threadIdx.x;
    if (e < E) {
        int s = ei[e];
        int d = ei[E + e];
        int pos = atomicAdd(&g_cursor[d], 1);
        g_csr[pos] = s;
    }
}

// ---------------------------------------------------------------------------
// GEMM1 (tensor cores, fp16 mma.m16n8k16): H1pre = dinv * (x @ W1), fp16 out.
// 512 thr = 16 warps; warp (wr,wc): rows wr*16..+15, cols wc*32..+31.
// Halved per-warp accumulator (16 regs) -> lower reg pressure -> higher occ,
// staging latency hidden by concurrent blocks.
#define XS_STRIDE 36   // half2-words per row (32 data + 4 pad)
#define WT_STRIDE 68   // half2-words per col (64 data + 4 pad)
__global__ __launch_bounds__(512) void k_gemm1(const float* __restrict__ x,
                                               const float* __restrict__ W,
                                               int N) {
    __shared__ u32 xs[128 * XS_STRIDE];   // 18.4 KB
    __shared__ u32 Wt[HID_F * WT_STRIDE]; // 17.4 KB
    int t = threadIdx.x;
    int warp = t >> 5, lane = t & 31;
    int wr = warp >> 1;      // row group 0..7
    int wc = warp & 1;       // col half 0..1
    int gr = lane >> 2, gc = lane & 3;
    int row_base = blockIdx.x * 128 + wr * 16;

    // stage Wt: W[k][n] fp32 -> Wt[n][k/2] half2. coalesced reads over n.
    for (int i = t; i < HID_F * (IN_F / 2); i += 512) {   // i = kw*64 + n
        int kw = i >> 6, n = i & 63;
        float lo = W[(2 * kw) * HID_F + n];
        float hi = W[(2 * kw + 1) * HID_F + n];
        __half2 h = __floats2half2_rn(lo, hi);
        Wt[n * WT_STRIDE + kw] = *(u32*)&h;
    }

    float acc[4][4];
    #pragma unroll
    for (int nt = 0; nt < 4; ++nt)
        #pragma unroll
        for (int c = 0; c < 4; ++c) acc[nt][c] = 0.f;

    #pragma unroll
    for (int kc = 0; kc < IN_F; kc += 64) {
        __syncthreads();
        // stage x chunk: 128 rows x 64 floats -> fp16. coalesced LDG.128.
        for (int i = t; i < 128 * 16; i += 512) {   // i = r*16 + q
            int r = i >> 4, q = i & 15;
            int row = blockIdx.x * 128 + r;
            float4 v = make_float4(0.f, 0.f, 0.f, 0.f);
            if (row < N) v = *(const float4*)&x[(size_t)row * IN_F + kc + q * 4];
            __half2 h0 = __floats2half2_rn(v.x, v.y);
            __half2 h1 = __floats2half2_rn(v.z, v.w);
            *(uint2*)&xs[r * XS_STRIDE + q * 2] =
                make_uint2(*(u32*)&h0, *(u32*)&h1);
        }
        __syncthreads();
        #pragma unroll
        for (int ks = 0; ks < 4; ++ks) {            // 4 x k16 per chunk
            int kw0 = ks * 8;
            u32 a0 = xs[(wr * 16 + gr)     * XS_STRIDE + kw0 + gc];
            u32 a1 = xs[(wr * 16 + gr + 8) * XS_STRIDE + kw0 + gc];
            u32 a2 = xs[(wr * 16 + gr)     * XS_STRIDE + kw0 + gc + 4];
            u32 a3 = xs[(wr * 16 + gr + 8) * XS_STRIDE + kw0 + gc + 4];
            int kwG = (kc >> 1) + kw0;
            #pragma unroll
            for (int nt = 0; nt < 4; ++nt) {
                int ncol = wc * 32 + nt * 8;
                u32 b0 = Wt[(ncol + gr) * WT_STRIDE + kwG + gc];
                u32 b1 = Wt[(ncol + gr) * WT_STRIDE + kwG + gc + 4];
                asm("mma.sync.aligned.m16n8k16.row.col.f32.f16.f16.f32 "
                    "{%0,%1,%2,%3}, {%4,%5,%6,%7}, {%8,%9}, {%0,%1,%2,%3};"
                    : "+f"(acc[nt][0]), "+f"(acc[nt][1]),
                      "+f"(acc[nt][2]), "+f"(acc[nt][3])
                    : "r"(a0), "r"(a1), "r"(a2), "r"(a3), "r"(b0), "r"(b1));
            }
        }
    }
    // epilogue: c0,c1 -> row gr cols (2gc,2gc+1); c2,c3 -> row gr+8
    int r0 = row_base + gr;
    int r1 = r0 + 8;
    if (r0 < N) {
        float dv = g_dinv[r0];
        #pragma unroll
        for (int nt = 0; nt < 4; ++nt) {
            __half2 h = __floats2half2_rn(dv * acc[nt][0], dv * acc[nt][1]);
            *(u32*)&g_H1h[(size_t)r0 * HID_F + wc * 32 + nt * 8 + 2 * gc] = *(u32*)&h;
        }
    }
    if (r1 < N) {
        float dv = g_dinv[r1];
        #pragma unroll
        for (int nt = 0; nt < 4; ++nt) {
            __half2 h = __floats2half2_rn(dv * acc[nt][2], dv * acc[nt][3]);
            *(u32*)&g_H1h[(size_t)r1 * HID_F + wc * 32 + nt * 8 + 2 * gc] = *(u32*)&h;
        }
    }
}

// GEMM2: H2pre[N,32] = dinv * (agg1[N,64] @ W2[64,32]); fp32 math, fp16 store
__global__ __launch_bounds__(256) void k_gemm2(const float* __restrict__ W, int N) {
    __shared__ float Ws[HID_F * OUT_F];
    __shared__ float xs2[32 * HID_F];
    int t = threadIdx.x;
    for (int i = t; i < HID_F * OUT_F; i += 256) Ws[i] = W[i];

    int row0 = blockIdx.x * 32;
    int rows = N - row0; if (rows > 32) rows = 32;

    const float4* xg  = (const float4*)(g_agg1 + (size_t)row0 * HID_F);
    float4*       xs4 = (float4*)xs2;
    const int NV = 32 * HID_F / 4;
    for (int i = t; i < NV; i += 256) {
        int r = i / (HID_F / 4);
        xs4[i] = (r < rows) ? xg[i] : make_float4(0.f, 0.f, 0.f, 0.f);
    }
    __syncthreads();

    int r = t >> 3;
    int g = (t & 7) * 4;
    if (r < rows) {
        u64 a01 = 0ull, a23 = 0ull;
        #pragma unroll 16
        for (int k = 0; k < HID_F; ++k) {
            float xv = xs2[r * HID_F + k];
            u64 xp  = pack2(xv, xv);
            u64 w01 = *(const u64*)&Ws[k * OUT_F + g];
            u64 w23 = *(const u64*)&Ws[k * OUT_F + g + 2];
            fma2(a01, xp, w01);
            fma2(a23, xp, w23);
        }
        float2 f01 = unpack2(a01);
        float2 f23 = unpack2(a23);
        float dv = g_dinv[row0 + r];
        __half2 h01 = __floats2half2_rn(dv * f01.x, dv * f01.y);
        __half2 h23 = __floats2half2_rn(dv * f23.x, dv * f23.y);
        *(uint2*)&g_H2h[(size_t)(row0 + r) * OUT_F + g] =
            make_uint2(*(u32*)&h01, *(u32*)&h23);
    }
}

// ---------------------------------------------------------------------------
// Gather1: quarter-warp per node (4 nodes/warp), 8 lanes x 8 fp16 feats.
// Weightless inner loop. Epilogue: relu(dinv[n]*acc + b1).
__global__ __launch_bounds__(256) void k_gather1(const float* __restrict__ b1, int N) {
    int w    = (blockIdx.x * blockDim.x + threadIdx.x) >> 5;
    int lane = threadIdx.x & 31;
    int h    = lane >> 3;
    int hl   = lane & 7;
    int n    = 4 * w + h;
    bool active = (n < N);
    int nn = active ? n : 0;

    uint4 sh = *(const uint4*)&g_H1h[(size_t)nn * HID_F + hl * 8];
    float2 s0 = __half22float2(*(__half2*)&sh.x);
    float2 s1 = __half22float2(*(__half2*)&sh.y);
    float2 s2 = __half22float2(*(__half2*)&sh.z);
    float2 s3 = __half22float2(*(__half2*)&sh.w);
    u64 acc0 = pack2(s0.x, s0.y);
    u64 acc1 = pack2(s1.x, s1.y);
    u64 acc2 = pack2(s2.x, s2.y);
    u64 acc3 = pack2(s3.x, s3.y);

    int start = active ? g_rowstart[nn] : 0;
    int cnt   = active ? g_deg[nn] : 0;
    int m = cnt;
    m = max(m, __shfl_xor_sync(0xffffffffu, m, 8));
    m = max(m, __shfl_xor_sync(0xffffffffu, m, 16));

    for (int base = 0; base < m; base += 8) {
        int sl = 0;
        if (base + hl < cnt) sl = g_csr[start + base + hl];
        int remw = m - base; if (remw > 8) remw = 8;
        int remh = cnt - base;
        #pragma unroll 4
        for (int k = 0; k < remw; ++k) {
            int sk = __shfl_sync(0xffffffffu, sl, h * 8 + k);
            if (k < remh) {
                uint4 hv = *(const uint4*)&g_H1h[(size_t)sk * HID_F + hl * 8];
                float2 v0 = __half22float2(*(__half2*)&hv.x);
                float2 v1 = __half22float2(*(__half2*)&hv.y);
                float2 v2 = __half22float2(*(__half2*)&hv.z);
                float2 v3 = __half22float2(*(__half2*)&hv.w);
                add2(acc0, pack2(v0.x, v0.y));
                add2(acc1, pack2(v1.x, v1.y));
                add2(acc2, pack2(v2.x, v2.y));
                add2(acc3, pack2(v3.x, v3.y));
            }
        }
    }
    if (active) {
        float dn = g_dinv[n];
        float4 ba = *(const float4*)&b1[hl * 8];
        float4 bc = *(const float4*)&b1[hl * 8 + 4];
        float2 a0 = unpack2(acc0), a1 = unpack2(acc1);
        float2 a2 = unpack2(acc2), a3 = unpack2(acc3);
        *(float4*)&g_agg1[(size_t)n * HID_F + hl * 8] =
            make_float4(fmaxf(fmaf(dn, a0.x, ba.x), 0.f),
                        fmaxf(fmaf(dn, a0.y, ba.y), 0.f),
                        fmaxf(fmaf(dn, a1.x, ba.z), 0.f),
                        fmaxf(fmaf(dn, a1.y, ba.w), 0.f));
        *(float4*)&g_agg1[(size_t)n * HID_F + hl * 8 + 4] =
            make_float4(fmaxf(fmaf(dn, a2.x, bc.x), 0.f),
                        fmaxf(fmaf(dn, a2.y, bc.y), 0.f),
                        fmaxf(fmaf(dn, a3.x, bc.z), 0.f),
                        fmaxf(fmaf(dn, a3.y, bc.w), 0.f));
    }
}

// Gather2: EIGHTH-warp per node (8 nodes/warp), 4 lanes x 8 fp16 feats
// (uint4 per edge; 8 edges per warp-iteration). Writes d_out; zeroes g_deg.
__global__ __launch_bounds__(256) void k_gather2(const float* __restrict__ b2,
                                                 float* __restrict__ out, int N) {
    int w    = (blockIdx.x * blockDim.x + threadIdx.x) >> 5;
    int lane = threadIdx.x & 31;
    int h    = lane >> 2;          // eighth id 0..7
    int hl   = lane & 3;           // lane within eighth
    int n    = 8 * w + h;
    bool active = (n < N);
    int nn = active ? n : 0;

    uint4 sh = *(const uint4*)&g_H2h[(size_t)nn * OUT_F + hl * 8];
    float2 s0 = __half22float2(*(__half2*)&sh.x);
    float2 s1 = __half22float2(*(__half2*)&sh.y);
    float2 s2 = __half22float2(*(__half2*)&sh.z);
    float2 s3 = __half22float2(*(__half2*)&sh.w);
    u64 acc0 = pack2(s0.x, s0.y);
    u64 acc1 = pack2(s1.x, s1.y);
    u64 acc2 = pack2(s2.x, s2.y);
    u64 acc3 = pack2(s3.x, s3.y);

    int start = active ? g_rowstart[nn] : 0;
    int cnt   = active ? g_deg[nn] : 0;
    int m = cnt;
    m = max(m, __shfl_xor_sync(0xffffffffu, m, 4));
    m = max(m, __shfl_xor_sync(0xffffffffu, m, 8));
    m = max(m, __shfl_xor_sync(0xffffffffu, m, 16));   // warp-uniform max

    for (int base = 0; base < m; base += 4) {
        int sl = 0;
        if (base + hl < cnt) sl = g_csr[start + base + hl];
        int remw = m - base; if (remw > 4) remw = 4;   // warp-uniform
        int remh = cnt - base;                          // per-eighth
        #pragma unroll 4
        for (int k = 0; k < remw; ++k) {
            int sk = __shfl_sync(0xffffffffu, sl, h * 4 + k);
            if (k < remh) {
                uint4 hv = *(const uint4*)&g_H2h[(size_t)sk * OUT_F + hl * 8];
                float2 v0 = __half22float2(*(__half2*)&hv.x);
                float2 v1 = __half22float2(*(__half2*)&hv.y);
                float2 v2 = __half22float2(*(__half2*)&hv.z);
                float2 v3 = __half22float2(*(__half2*)&hv.w);
                add2(acc0, pack2(v0.x, v0.y));
                add2(acc1, pack2(v1.x, v1.y));
                add2(acc2, pack2(v2.x, v2.y));
                add2(acc3, pack2(v3.x, v3.y));
            }
        }
    }
    if (active) {
        float dn = g_dinv[n];
        float4 ba = *(const float4*)&b2[hl * 8];
        float4 bc = *(const float4*)&b2[hl * 8 + 4];
        float2 a0 = unpack2(acc0), a1 = unpack2(acc1);
        float2 a2 = unpack2(acc2), a3 = unpack2(acc3);
        *(float4*)&out[(size_t)n * OUT_F + hl * 8] =
            make_float4(fmaf(dn, a0.x, ba.x), fmaf(dn, a0.y, ba.y),
                        fmaf(dn, a1.x, ba.z), fmaf(dn, a1.y, ba.w));
        *(float4*)&out[(size_t)n * OUT_F + hl * 8 + 4] =
            make_float4(fmaf(dn, a2.x, bc.x), fmaf(dn, a2.y, bc.y),
                        fmaf(dn, a3.x, bc.z), fmaf(dn, a3.y, bc.w));
        if (hl == 0) g_deg[n] = 0;    // restore invariant for next launch
    }
}

// ---------------------------------------------------------------------------
extern "C" void kernel_launch(void* const* d_in, const int* in_sizes, int n_in,
                              void* d_out, int out_size) {
    const float* x  = (const float*)d_in[0];
    const int*   ei = (const int*)d_in[1];      // int32 (JAX x64 disabled)
    const float* W1 = (const float*)d_in[2];
    const float* b1 = (const float*)d_in[3];
    const float* W2 = (const float*)d_in[4];
    const float* b2 = (const float*)d_in[5];
    float*       out = (float*)d_out;

    const int N = in_sizes[0] / IN_F;     // 100000
    const int E = in_sizes[1] / 2;        // 1600000
    const int NB = (N + 255) / 256;

    const int T = 256;
    k_edge_prep<<<(E + T - 1) / T, T>>>(ei, E);     // deg starts zero
    k_scan_a<<<NB, 256>>>(N);                       // computes dinv
    k_scan_b<<<1, 512>>>(NB);
    k_gemm1  <<<(N + 127) / 128, 512>>>(x, W1, N);  // 4th launch (profiled; needs dinv)
    k_scan_c<<<NB, 256>>>(N);
    k_fill  <<<(E + T - 1) / T, T>>>(ei, E);

    k_gather1<<<(N + 31) / 32, 256>>>(b1, N);

    k_gemm2  <<<(N + 31) / 32, 256>>>(W2, N);
    k_gather2<<<(N + 63) / 64, 256>>>(b2, out, N);  // zeroes g_deg at end
}